// round 12
// baseline (speedup 1.0000x reference)
#include <cuda_runtime.h>
#include <cuda_fp16.h>
#include <cstdint>

#define NNODES 20000
#define NC 32
#define ND 128
#define ROWH 272        // fp16 smem row pitch in BYTES (136 halfs): conflict-free

// ---- smem byte offsets ----
#define SUH 0                    // fp16 u tile 128 x 272 = 34816
#define SMH 34816                // fp16 mean 4 x 272     = 1088
#define SZ2 35904                // fp32 z2 4 x 128 x 4   = 2048
#define SZ3 37952                // fp32 z3               = 2048
#define SB1 40000                // fp32 b1               = 512
#define SMEM_BYTES 40512         // x3 CTAs = 121536 <= 228KB/SM

// ---- device scratch: fragment-permuted fp16 weights (round-7 layout) ----
__device__ uint4 g_W1h[2048];    // 32 KB  (W1 + I folded)
__device__ uint4 g_W23h[4096];   // 64 KB  ([W2;W3])

__device__ __forceinline__ uint32_t pk(float a, float b) {
    __half2 h = __floats2half2_rn(a, b);
    return *(uint32_t*)&h;
}

__device__ __forceinline__ void mma_f16(float* d, const uint32_t* a,
                                        uint32_t b0, uint32_t b1) {
    asm volatile(
        "mma.sync.aligned.m16n8k16.row.col.f32.f16.f16.f32 "
        "{%0,%1,%2,%3}, {%4,%5,%6,%7}, {%8,%9}, {%0,%1,%2,%3};\n"
        : "+f"(d[0]), "+f"(d[1]), "+f"(d[2]), "+f"(d[3])
        : "r"(a[0]), "r"(a[1]), "r"(a[2]), "r"(a[3]), "r"(b0), "r"(b1));
}

__device__ __forceinline__ void ldsm_x4(uint32_t* r, uint32_t addr) {
    asm volatile(
        "ldmatrix.sync.aligned.m8n8.x4.shared.b16 {%0,%1,%2,%3}, [%4];"
        : "=r"(r[0]), "=r"(r[1]), "=r"(r[2]), "=r"(r[3]) : "r"(addr));
}

// ============================================================================
// prep: fragment-permuted fp16 weight images; W1 gets +I (residual folded)
// ============================================================================
__global__ void prep_kernel(const float* __restrict__ W1,
                            const float* __restrict__ W2,
                            const float* __restrict__ W3) {
    int t0 = blockIdx.x * blockDim.x + threadIdx.x;
    int stride = gridDim.x * blockDim.x;
    for (int i = t0; i < 2048; i += stride) {
        int lane = i & 31, ks = (i >> 5) & 7, ntp = (i >> 8) & 3, wE = i >> 10;
        int g = lane >> 2, tg = lane & 3;
        int e0 = wE * 64 + ntp * 16 + g, e1 = e0 + 8;
        int kb = ks * 16 + 2 * tg;
        uint4 v;
        v.x = pk(W1[e0 * ND + kb]     + (e0 == kb     ? 1.f : 0.f),
                 W1[e0 * ND + kb + 1] + (e0 == kb + 1 ? 1.f : 0.f));
        v.y = pk(W1[e0 * ND + kb + 8] + (e0 == kb + 8 ? 1.f : 0.f),
                 W1[e0 * ND + kb + 9] + (e0 == kb + 9 ? 1.f : 0.f));
        v.z = pk(W1[e1 * ND + kb]     + (e1 == kb     ? 1.f : 0.f),
                 W1[e1 * ND + kb + 1] + (e1 == kb + 1 ? 1.f : 0.f));
        v.w = pk(W1[e1 * ND + kb + 8] + (e1 == kb + 8 ? 1.f : 0.f),
                 W1[e1 * ND + kb + 9] + (e1 == kb + 9 ? 1.f : 0.f));
        g_W1h[i] = v;
    }
    for (int i = t0; i < 4096; i += stride) {
        int lane = i & 31, ks = (i >> 5) & 7, ntp = (i >> 8) & 1, w = i >> 9;
        int g = lane >> 2, tg = lane & 3;
        int e0 = w * 32 + ntp * 16 + g, e1 = e0 + 8;
        int kb = ks * 16 + 2 * tg;
        const float* r0 = (e0 < 128) ? (W2 + e0 * ND) : (W3 + (e0 - 128) * ND);
        const float* r1 = (e1 < 128) ? (W2 + e1 * ND) : (W3 + (e1 - 128) * ND);
        uint4 v;
        v.x = pk(r0[kb], r0[kb + 1]);
        v.y = pk(r0[kb + 8], r0[kb + 9]);
        v.z = pk(r1[kb], r1[kb + 1]);
        v.w = pk(r1[kb + 8], r1[kb + 9]);
        g_W23h[i] = v;
    }
}

// ============================================================================
// Fused kernel: 4 nodes (128 rows)/CTA, 128 threads (4 warps), 64x64 warp
// tiles; warp-per-node staging with fused mean; ldmatrix A fragments.
// ============================================================================
__global__ void __launch_bounds__(128)
fused_kernel(const float* __restrict__ u,
             const float* __restrict__ mask,
             const float* __restrict__ normalizer,
             const int* __restrict__ coloring,
             const float* __restrict__ b1,
             float* __restrict__ out) {
    extern __shared__ char smem[];
    float* sZ2 = (float*)(smem + SZ2);
    float* sZ3 = (float*)(smem + SZ3);
    float* sB1 = (float*)(smem + SB1);

    const int t = threadIdx.x;
    const int rowBase = blockIdx.x * 128;
    const int nodeBase = blockIdx.x * 4;

    const int w = t >> 5, lane = t & 31;
    const int g = lane >> 2, tg = lane & 3;

    // ---- stage u -> fp16 tile, warp = node, mean fused into the load ----
    {
        const float4* up = (const float4*)(u + (long long)(nodeBase + w) * (NC * ND)) + lane;
        char* rowp = smem + SUH + (w * 32) * ROWH + lane * 8;
        float4 s = make_float4(0.f, 0.f, 0.f, 0.f);
#pragma unroll
        for (int c = 0; c < NC; c++) {
            float4 v = up[c * 32];
            s.x += v.x; s.y += v.y; s.z += v.z; s.w += v.w;
            uint2 h;
            h.x = pk(v.x, v.y);
            h.y = pk(v.z, v.w);
            *(uint2*)(rowp + c * ROWH) = h;
        }
        const float inv = 1.f / normalizer[nodeBase + w];
        uint2 m;
        m.x = pk(s.x * inv, s.y * inv);
        m.y = pk(s.z * inv, s.w * inv);
        *(uint2*)(smem + SMH + w * ROWH + lane * 8) = m;
    }
    if (t < 32) *(float4*)(sB1 + t * 4) = ((const float4*)b1)[t];
    __syncthreads();

    // ---- z2/z3: mean(4x128, M-pad 16) @ [W2;W3]^T via fp16 mma ----
    {
        const char* Ab = smem + SMH + g * ROWH + tg * 4;
        const bool valid = (g < 4);
#pragma unroll
        for (int rep = 0; rep < 2; rep++) {
            const int wz = w + rep * 4;        // e-slice 0..7
            float zacc[4][4];
#pragma unroll
            for (int n = 0; n < 4; n++)
#pragma unroll
                for (int r = 0; r < 4; r++) zacc[n][r] = 0.f;

            const uint4* Bp = g_W23h + wz * 512 + lane;
#pragma unroll
            for (int ks = 0; ks < 8; ks++) {
                uint32_t a[4];
                a[0] = valid ? *(const uint32_t*)(Ab + ks * 32) : 0u;
                a[1] = 0u;                      // rows 8..15 padding
                a[2] = valid ? *(const uint32_t*)(Ab + ks * 32 + 16) : 0u;
                a[3] = 0u;
#pragma unroll
                for (int ntp = 0; ntp < 2; ntp++) {
                    uint4 bb = Bp[ntp * 256 + ks * 32];
                    mma_f16(zacc[2 * ntp + 0], a, bb.x, bb.y);
                    mma_f16(zacc[2 * ntp + 1], a, bb.z, bb.w);
                }
            }
            if (valid) {
#pragma unroll
                for (int nt = 0; nt < 4; nt++) {
                    int e = wz * 32 + nt * 8 + tg * 2;
                    float2 v = make_float2(0.1f * zacc[nt][0], 0.1f * zacc[nt][1]);
                    if (e < 128) *(float2*)(sZ2 + g * ND + e) = v;
                    else         *(float2*)(sZ3 + g * ND + (e - 128)) = v;
                }
            }
        }
    }
    // (no barrier: sZ consumed after the post-GEMM barrier)

    // ---- main GEMM: warp tile 64x64: fp16(u) @ fp16(W1+I)^T, ldmatrix A ----
    const int warpM = w >> 1, warpE = w & 1;

    float acc[4][8][4];
#pragma unroll
    for (int mt = 0; mt < 4; mt++)
#pragma unroll
        for (int nt = 0; nt < 8; nt++)
#pragma unroll
            for (int r = 0; r < 4; r++) acc[mt][nt][r] = 0.f;

    // ldmatrix: lanes 0-15 -> rows lane&15 of the 16-row block (col 0);
    // lanes 16-31 -> same rows, +16B (k=8..15). Row pitch 272B, 16B-aligned.
    const uint32_t aAddr0 =
        (uint32_t)__cvta_generic_to_shared(smem + SUH) +
        (warpM * 64 + (lane & 15)) * ROWH + (lane >> 4) * 16;
    const uint4* Bbase = g_W1h + warpE * 1024 + lane;

#pragma unroll
    for (int ks = 0; ks < 8; ks++) {
        uint32_t a[4][4];
#pragma unroll
        for (int mt = 0; mt < 4; mt++)
            ldsm_x4(a[mt], aAddr0 + mt * 16 * ROWH + ks * 32);
#pragma unroll
        for (int ntp = 0; ntp < 4; ntp++) {
            uint4 bb = Bbase[ntp * 256 + ks * 32];
#pragma unroll
            for (int mt = 0; mt < 4; mt++) {
                mma_f16(acc[mt][2 * ntp + 0], a[mt], bb.x, bb.y);
                mma_f16(acc[mt][2 * ntp + 1], a[mt], bb.z, bb.w);
            }
        }
    }

    __syncthreads();   // sZ2/sZ3 visible

    // ---- epilogue: + b1 + mask*z3 + (c==mycol)*z2 (residual in GEMM) ----
    const int nA = warpM * 2, nB = nA + 1;
    const int colA = __ldg(coloring + nodeBase + nA);
    const int colB = __ldg(coloring + nodeBase + nB);

    float mk[4][2];
    bool  hit[4][2];
    int   lrow[4][2];
#pragma unroll
    for (int mt = 0; mt < 4; mt++)
#pragma unroll
        for (int half = 0; half < 2; half++) {
            int r = warpM * 64 + mt * 16 + half * 8 + g;
            int c = r & 31;
            lrow[mt][half] = r;
            mk[mt][half]  = __ldg(mask + rowBase + r);
            hit[mt][half] = (c == ((mt < 2) ? colA : colB));
        }

#pragma unroll
    for (int nt = 0; nt < 8; nt++) {
        const int e = warpE * 64 + nt * 8 + tg * 2;
        const float2 bv   = *(const float2*)(sB1 + e);
        const float2 z2A  = *(const float2*)(sZ2 + nA * ND + e);
        const float2 z3A  = *(const float2*)(sZ3 + nA * ND + e);
        const float2 z2B  = *(const float2*)(sZ2 + nB * ND + e);
        const float2 z3B  = *(const float2*)(sZ3 + nB * ND + e);
#pragma unroll
        for (int mt = 0; mt < 4; mt++) {
            const float2 z2v = (mt < 2) ? z2A : z2B;
            const float2 z3v = (mt < 2) ? z3A : z3B;
#pragma unroll
            for (int half = 0; half < 2; half++) {
                const int r = lrow[mt][half];
                float v0 = acc[mt][nt][half * 2 + 0] + bv.x + mk[mt][half] * z3v.x;
                float v1 = acc[mt][nt][half * 2 + 1] + bv.y + mk[mt][half] * z3v.y;
                if (hit[mt][half]) { v0 += z2v.x; v1 += z2v.y; }
                *(float2*)(out + (long long)(rowBase + r) * ND + e) =
                    make_float2(v0, v1);
            }
        }
    }
}

// ============================================================================
extern "C" void kernel_launch(void* const* d_in, const int* in_sizes, int n_in,
                              void* d_out, int out_size) {
    const float* u    = (const float*)d_in[0];
    const float* mask = (const float*)d_in[1];
    const float* norm = (const float*)d_in[2];
    const int*   col  = (const int*)d_in[3];
    const float* W1   = (const float*)d_in[4];
    const float* b1   = (const float*)d_in[5];
    const float* W2   = (const float*)d_in[6];
    const float* W3   = (const float*)d_in[7];
    float* out = (float*)d_out;

    static bool attr_set = false;
    if (!attr_set) {
        cudaFuncSetAttribute(fused_kernel,
                             cudaFuncAttributeMaxDynamicSharedMemorySize,
                             SMEM_BYTES);
        attr_set = true;
    }

    prep_kernel<<<24, 256>>>(W1, W2, W3);
    fused_kernel<<<NNODES / 4, 128, SMEM_BYTES>>>(u, mask, norm, col, b1, out);

    (void)in_sizes; (void)n_in; (void)out_size;
}

// round 13
// speedup vs baseline: 1.1628x; 1.1628x over previous
#include <cuda_runtime.h>
#include <cuda_fp16.h>
#include <cstdint>

#define NNODES 20000
#define NC 32
#define ND 128
#define ROWH 272        // fp16 smem row pitch in BYTES (136 halfs): conflict-free

// ---- smem byte offsets ----
#define SUH 0                    // fp16 u tile 128 x 272 = 34816
#define SMH 34816                // fp16 mean 4 x 272     = 1088
#define SZ2 35904                // fp32 z2 4 x 128 x 4   = 2048
#define SZ3 37952                // fp32 z3               = 2048
#define SB1 40000                // fp32 b1               = 512
#define SMEM_BYTES 40512         // x3 CTAs = 121536 <= 228KB/SM

// ---- device scratch: fragment-permuted fp16 weights (round-7 layout) ----
__device__ uint4 g_W1h[2048];    // 32 KB  (W1 + I folded)
__device__ uint4 g_W23h[4096];   // 64 KB  ([W2;W3])

__device__ __forceinline__ uint32_t pk(float a, float b) {
    __half2 h = __floats2half2_rn(a, b);
    return *(uint32_t*)&h;
}

__device__ __forceinline__ void mma_f16(float* d, const uint32_t* a,
                                        uint32_t b0, uint32_t b1) {
    asm volatile(
        "mma.sync.aligned.m16n8k16.row.col.f32.f16.f16.f32 "
        "{%0,%1,%2,%3}, {%4,%5,%6,%7}, {%8,%9}, {%0,%1,%2,%3};\n"
        : "+f"(d[0]), "+f"(d[1]), "+f"(d[2]), "+f"(d[3])
        : "r"(a[0]), "r"(a[1]), "r"(a[2]), "r"(a[3]), "r"(b0), "r"(b1));
}

__device__ __forceinline__ void ldsm_x4(uint32_t* r, uint32_t addr) {
    asm volatile(
        "ldmatrix.sync.aligned.m8n8.x4.shared.b16 {%0,%1,%2,%3}, [%4];"
        : "=r"(r[0]), "=r"(r[1]), "=r"(r[2]), "=r"(r[3]) : "r"(addr));
}

// ============================================================================
// prep: fragment-permuted fp16 weight images; W1 gets +I (residual folded)
// ============================================================================
__global__ void prep_kernel(const float* __restrict__ W1,
                            const float* __restrict__ W2,
                            const float* __restrict__ W3) {
    int t0 = blockIdx.x * blockDim.x + threadIdx.x;
    int stride = gridDim.x * blockDim.x;
    for (int i = t0; i < 2048; i += stride) {
        int lane = i & 31, ks = (i >> 5) & 7, ntp = (i >> 8) & 3, wE = i >> 10;
        int g = lane >> 2, tg = lane & 3;
        int e0 = wE * 64 + ntp * 16 + g, e1 = e0 + 8;
        int kb = ks * 16 + 2 * tg;
        uint4 v;
        v.x = pk(W1[e0 * ND + kb]     + (e0 == kb     ? 1.f : 0.f),
                 W1[e0 * ND + kb + 1] + (e0 == kb + 1 ? 1.f : 0.f));
        v.y = pk(W1[e0 * ND + kb + 8] + (e0 == kb + 8 ? 1.f : 0.f),
                 W1[e0 * ND + kb + 9] + (e0 == kb + 9 ? 1.f : 0.f));
        v.z = pk(W1[e1 * ND + kb]     + (e1 == kb     ? 1.f : 0.f),
                 W1[e1 * ND + kb + 1] + (e1 == kb + 1 ? 1.f : 0.f));
        v.w = pk(W1[e1 * ND + kb + 8] + (e1 == kb + 8 ? 1.f : 0.f),
                 W1[e1 * ND + kb + 9] + (e1 == kb + 9 ? 1.f : 0.f));
        g_W1h[i] = v;
    }
    for (int i = t0; i < 4096; i += stride) {
        int lane = i & 31, ks = (i >> 5) & 7, ntp = (i >> 8) & 1, w = i >> 9;
        int g = lane >> 2, tg = lane & 3;
        int e0 = w * 32 + ntp * 16 + g, e1 = e0 + 8;
        int kb = ks * 16 + 2 * tg;
        const float* r0 = (e0 < 128) ? (W2 + e0 * ND) : (W3 + (e0 - 128) * ND);
        const float* r1 = (e1 < 128) ? (W2 + e1 * ND) : (W3 + (e1 - 128) * ND);
        uint4 v;
        v.x = pk(r0[kb], r0[kb + 1]);
        v.y = pk(r0[kb + 8], r0[kb + 9]);
        v.z = pk(r1[kb], r1[kb + 1]);
        v.w = pk(r1[kb + 8], r1[kb + 9]);
        g_W23h[i] = v;
    }
}

// ============================================================================
// Fused kernel: 4 nodes (128 rows)/CTA, 128 threads (4 warps), 64x64 warp
// tiles; warp-per-node staging with fused mean; ldmatrix A fragments.
// __launch_bounds__(128, 3) pins 3 CTAs/SM (caps regs at 168, no spill —
// verified by round-9's identical GEMM body at this bound).
// ============================================================================
__global__ void __launch_bounds__(128, 3)
fused_kernel(const float* __restrict__ u,
             const float* __restrict__ mask,
             const float* __restrict__ normalizer,
             const int* __restrict__ coloring,
             const float* __restrict__ b1,
             float* __restrict__ out) {
    extern __shared__ char smem[];
    float* sZ2 = (float*)(smem + SZ2);
    float* sZ3 = (float*)(smem + SZ3);
    float* sB1 = (float*)(smem + SB1);

    const int t = threadIdx.x;
    const int rowBase = blockIdx.x * 128;
    const int nodeBase = blockIdx.x * 4;

    const int w = t >> 5, lane = t & 31;
    const int g = lane >> 2, tg = lane & 3;

    // ---- stage u -> fp16 tile, warp = node, mean fused into the load ----
    {
        const float4* up = (const float4*)(u + (long long)(nodeBase + w) * (NC * ND)) + lane;
        char* rowp = smem + SUH + (w * 32) * ROWH + lane * 8;
        float4 s = make_float4(0.f, 0.f, 0.f, 0.f);
#pragma unroll
        for (int c = 0; c < NC; c++) {
            float4 v = up[c * 32];
            s.x += v.x; s.y += v.y; s.z += v.z; s.w += v.w;
            uint2 h;
            h.x = pk(v.x, v.y);
            h.y = pk(v.z, v.w);
            *(uint2*)(rowp + c * ROWH) = h;
        }
        const float inv = 1.f / normalizer[nodeBase + w];
        uint2 m;
        m.x = pk(s.x * inv, s.y * inv);
        m.y = pk(s.z * inv, s.w * inv);
        *(uint2*)(smem + SMH + w * ROWH + lane * 8) = m;
    }
    if (t < 32) *(float4*)(sB1 + t * 4) = ((const float4*)b1)[t];
    __syncthreads();

    // ---- z2/z3: mean(4x128, M-pad 16) @ [W2;W3]^T via fp16 mma ----
    {
        const char* Ab = smem + SMH + g * ROWH + tg * 4;
        const bool valid = (g < 4);
#pragma unroll
        for (int rep = 0; rep < 2; rep++) {
            const int wz = w + rep * 4;        // e-slice 0..7
            float zacc[4][4];
#pragma unroll
            for (int n = 0; n < 4; n++)
#pragma unroll
                for (int r = 0; r < 4; r++) zacc[n][r] = 0.f;

            const uint4* Bp = g_W23h + wz * 512 + lane;
#pragma unroll
            for (int ks = 0; ks < 8; ks++) {
                uint32_t a[4];
                a[0] = valid ? *(const uint32_t*)(Ab + ks * 32) : 0u;
                a[1] = 0u;                      // rows 8..15 padding
                a[2] = valid ? *(const uint32_t*)(Ab + ks * 32 + 16) : 0u;
                a[3] = 0u;
#pragma unroll
                for (int ntp = 0; ntp < 2; ntp++) {
                    uint4 bb = Bp[ntp * 256 + ks * 32];
                    mma_f16(zacc[2 * ntp + 0], a, bb.x, bb.y);
                    mma_f16(zacc[2 * ntp + 1], a, bb.z, bb.w);
                }
            }
            if (valid) {
#pragma unroll
                for (int nt = 0; nt < 4; nt++) {
                    int e = wz * 32 + nt * 8 + tg * 2;
                    float2 v = make_float2(0.1f * zacc[nt][0], 0.1f * zacc[nt][1]);
                    if (e < 128) *(float2*)(sZ2 + g * ND + e) = v;
                    else         *(float2*)(sZ3 + g * ND + (e - 128)) = v;
                }
            }
        }
    }
    // (no barrier: sZ consumed after the post-GEMM barrier)

    // ---- main GEMM: warp tile 64x64: fp16(u) @ fp16(W1+I)^T, ldmatrix A ----
    const int warpM = w >> 1, warpE = w & 1;

    float acc[4][8][4];
#pragma unroll
    for (int mt = 0; mt < 4; mt++)
#pragma unroll
        for (int nt = 0; nt < 8; nt++)
#pragma unroll
            for (int r = 0; r < 4; r++) acc[mt][nt][r] = 0.f;

    const uint32_t aAddr0 =
        (uint32_t)__cvta_generic_to_shared(smem + SUH) +
        (warpM * 64 + (lane & 15)) * ROWH + (lane >> 4) * 16;
    const uint4* Bbase = g_W1h + warpE * 1024 + lane;

#pragma unroll
    for (int ks = 0; ks < 8; ks++) {
        uint32_t a[4][4];
#pragma unroll
        for (int mt = 0; mt < 4; mt++)
            ldsm_x4(a[mt], aAddr0 + mt * 16 * ROWH + ks * 32);
#pragma unroll
        for (int ntp = 0; ntp < 4; ntp++) {
            uint4 bb = Bbase[ntp * 256 + ks * 32];
#pragma unroll
            for (int mt = 0; mt < 4; mt++) {
                mma_f16(acc[mt][2 * ntp + 0], a[mt], bb.x, bb.y);
                mma_f16(acc[mt][2 * ntp + 1], a[mt], bb.z, bb.w);
            }
        }
    }

    __syncthreads();   // sZ2/sZ3 visible

    // ---- epilogue: + b1 + mask*z3 + (c==mycol)*z2 (residual in GEMM) ----
    const int nA = warpM * 2, nB = nA + 1;
    const int colA = __ldg(coloring + nodeBase + nA);
    const int colB = __ldg(coloring + nodeBase + nB);

    float mk[4][2];
    bool  hit[4][2];
    int   lrow[4][2];
#pragma unroll
    for (int mt = 0; mt < 4; mt++)
#pragma unroll
        for (int half = 0; half < 2; half++) {
            int r = warpM * 64 + mt * 16 + half * 8 + g;
            int c = r & 31;
            lrow[mt][half] = r;
            mk[mt][half]  = __ldg(mask + rowBase + r);
            hit[mt][half] = (c == ((mt < 2) ? colA : colB));
        }

#pragma unroll
    for (int nt = 0; nt < 8; nt++) {
        const int e = warpE * 64 + nt * 8 + tg * 2;
        const float2 bv   = *(const float2*)(sB1 + e);
        const float2 z2A  = *(const float2*)(sZ2 + nA * ND + e);
        const float2 z3A  = *(const float2*)(sZ3 + nA * ND + e);
        const float2 z2B  = *(const float2*)(sZ2 + nB * ND + e);
        const float2 z3B  = *(const float2*)(sZ3 + nB * ND + e);
#pragma unroll
        for (int mt = 0; mt < 4; mt++) {
            const float2 z2v = (mt < 2) ? z2A : z2B;
            const float2 z3v = (mt < 2) ? z3A : z3B;
#pragma unroll
            for (int half = 0; half < 2; half++) {
                const int r = lrow[mt][half];
                float v0 = acc[mt][nt][half * 2 + 0] + bv.x + mk[mt][half] * z3v.x;
                float v1 = acc[mt][nt][half * 2 + 1] + bv.y + mk[mt][half] * z3v.y;
                if (hit[mt][half]) { v0 += z2v.x; v1 += z2v.y; }
                *(float2*)(out + (long long)(rowBase + r) * ND + e) =
                    make_float2(v0, v1);
            }
        }
    }
}

// ============================================================================
extern "C" void kernel_launch(void* const* d_in, const int* in_sizes, int n_in,
                              void* d_out, int out_size) {
    const float* u    = (const float*)d_in[0];
    const float* mask = (const float*)d_in[1];
    const float* norm = (const float*)d_in[2];
    const int*   col  = (const int*)d_in[3];
    const float* W1   = (const float*)d_in[4];
    const float* b1   = (const float*)d_in[5];
    const float* W2   = (const float*)d_in[6];
    const float* W3   = (const float*)d_in[7];
    float* out = (float*)d_out;

    static bool attr_set = false;
    if (!attr_set) {
        cudaFuncSetAttribute(fused_kernel,
                             cudaFuncAttributeMaxDynamicSharedMemorySize,
                             SMEM_BYTES);
        attr_set = true;
    }

    prep_kernel<<<24, 256>>>(W1, W2, W3);
    fused_kernel<<<NNODES / 4, 128, SMEM_BYTES>>>(u, mask, norm, col, b1, out);

    (void)in_sizes; (void)n_in; (void)out_size;
}

// round 14
// speedup vs baseline: 1.1934x; 1.0263x over previous
#include <cuda_runtime.h>
#include <cuda_fp16.h>
#include <cstdint>

#define NNODES 20000
#define NC 32
#define ND 128
#define ROWH 272        // fp16 smem row pitch in BYTES (136 halfs): conflict-free

// ---- smem byte offsets ----
#define SUH 0                    // fp16 u tile 128 x 272 = 34816
#define SMH 34816                // fp16 mean 4 x 272     = 1088
#define SZ2 35904                // fp32 z2 4 x 128 x 4   = 2048
#define SZ3 37952                // fp32 z3               = 2048
#define SB1 40000                // fp32 b1               = 512
#define SMEM_BYTES 40512         // x3 CTAs = 121536 <= 228KB/SM

// ---- device scratch: fragment-permuted fp16 weights (round-7 layout) ----
__device__ uint4 g_W1h[2048];    // 32 KB  (W1 + I folded)
__device__ uint4 g_W23h[4096];   // 64 KB  ([W2;W3])

__device__ __forceinline__ uint32_t pk(float a, float b) {
    __half2 h = __floats2half2_rn(a, b);
    return *(uint32_t*)&h;
}

__device__ __forceinline__ void mma_f16(float* d, const uint32_t* a,
                                        uint32_t b0, uint32_t b1) {
    asm volatile(
        "mma.sync.aligned.m16n8k16.row.col.f32.f16.f16.f32 "
        "{%0,%1,%2,%3}, {%4,%5,%6,%7}, {%8,%9}, {%0,%1,%2,%3};\n"
        : "+f"(d[0]), "+f"(d[1]), "+f"(d[2]), "+f"(d[3])
        : "r"(a[0]), "r"(a[1]), "r"(a[2]), "r"(a[3]), "r"(b0), "r"(b1));
}

// ============================================================================
// prep: fragment-permuted fp16 weight images; W1 gets +I (residual folded)
// ============================================================================
__global__ void prep_kernel(const float* __restrict__ W1,
                            const float* __restrict__ W2,
                            const float* __restrict__ W3) {
    int t0 = blockIdx.x * blockDim.x + threadIdx.x;
    int stride = gridDim.x * blockDim.x;
    for (int i = t0; i < 2048; i += stride) {
        int lane = i & 31, ks = (i >> 5) & 7, ntp = (i >> 8) & 3, wE = i >> 10;
        int g = lane >> 2, tg = lane & 3;
        int e0 = wE * 64 + ntp * 16 + g, e1 = e0 + 8;
        int kb = ks * 16 + 2 * tg;
        uint4 v;
        v.x = pk(W1[e0 * ND + kb]     + (e0 == kb     ? 1.f : 0.f),
                 W1[e0 * ND + kb + 1] + (e0 == kb + 1 ? 1.f : 0.f));
        v.y = pk(W1[e0 * ND + kb + 8] + (e0 == kb + 8 ? 1.f : 0.f),
                 W1[e0 * ND + kb + 9] + (e0 == kb + 9 ? 1.f : 0.f));
        v.z = pk(W1[e1 * ND + kb]     + (e1 == kb     ? 1.f : 0.f),
                 W1[e1 * ND + kb + 1] + (e1 == kb + 1 ? 1.f : 0.f));
        v.w = pk(W1[e1 * ND + kb + 8] + (e1 == kb + 8 ? 1.f : 0.f),
                 W1[e1 * ND + kb + 9] + (e1 == kb + 9 ? 1.f : 0.f));
        g_W1h[i] = v;
    }
    for (int i = t0; i < 4096; i += stride) {
        int lane = i & 31, ks = (i >> 5) & 7, ntp = (i >> 8) & 1, w = i >> 9;
        int g = lane >> 2, tg = lane & 3;
        int e0 = w * 32 + ntp * 16 + g, e1 = e0 + 8;
        int kb = ks * 16 + 2 * tg;
        const float* r0 = (e0 < 128) ? (W2 + e0 * ND) : (W3 + (e0 - 128) * ND);
        const float* r1 = (e1 < 128) ? (W2 + e1 * ND) : (W3 + (e1 - 128) * ND);
        uint4 v;
        v.x = pk(r0[kb], r0[kb + 1]);
        v.y = pk(r0[kb + 8], r0[kb + 9]);
        v.z = pk(r1[kb], r1[kb + 1]);
        v.w = pk(r1[kb + 8], r1[kb + 9]);
        g_W23h[i] = v;
    }
}

// ============================================================================
// Fused kernel (round-11 structure): 4 nodes (128 rows)/CTA, 128 threads,
// 64x64 warp tiles, warp-per-node staging with fused mean.
// NEW: streaming cache policy on the zero-reuse streams (u: __ldcs,
// out: __stcs) to keep the hot weight set resident in L2/L1.
// ============================================================================
__global__ void __launch_bounds__(128)
fused_kernel(const float* __restrict__ u,
             const float* __restrict__ mask,
             const float* __restrict__ normalizer,
             const int* __restrict__ coloring,
             const float* __restrict__ b1,
             float* __restrict__ out) {
    extern __shared__ char smem[];
    float* sZ2 = (float*)(smem + SZ2);
    float* sZ3 = (float*)(smem + SZ3);
    float* sB1 = (float*)(smem + SB1);

    const int t = threadIdx.x;
    const int rowBase = blockIdx.x * 128;
    const int nodeBase = blockIdx.x * 4;

    const int w = t >> 5, lane = t & 31;
    const int g = lane >> 2, tg = lane & 3;

    // ---- stage u -> fp16 tile, warp = node, mean fused into the load ----
    {
        const float4* up = (const float4*)(u + (long long)(nodeBase + w) * (NC * ND)) + lane;
        char* rowp = smem + SUH + (w * 32) * ROWH + lane * 8;
        float4 s = make_float4(0.f, 0.f, 0.f, 0.f);
#pragma unroll
        for (int c = 0; c < NC; c++) {
            float4 v = __ldcs(up + c * 32);     // streaming: no L2 retention
            s.x += v.x; s.y += v.y; s.z += v.z; s.w += v.w;
            uint2 h;
            h.x = pk(v.x, v.y);
            h.y = pk(v.z, v.w);
            *(uint2*)(rowp + c * ROWH) = h;
        }
        const float inv = 1.f / normalizer[nodeBase + w];
        uint2 m;
        m.x = pk(s.x * inv, s.y * inv);
        m.y = pk(s.z * inv, s.w * inv);
        *(uint2*)(smem + SMH + w * ROWH + lane * 8) = m;
    }
    if (t < 32) *(float4*)(sB1 + t * 4) = ((const float4*)b1)[t];
    __syncthreads();

    // ---- z2/z3: mean(4x128, M-pad 16) @ [W2;W3]^T via fp16 mma ----
    {
        const char* Ab = smem + SMH + g * ROWH + tg * 4;
        const bool valid = (g < 4);
#pragma unroll
        for (int rep = 0; rep < 2; rep++) {
            const int wz = w + rep * 4;        // e-slice 0..7
            float zacc[4][4];
#pragma unroll
            for (int n = 0; n < 4; n++)
#pragma unroll
                for (int r = 0; r < 4; r++) zacc[n][r] = 0.f;

            const uint4* Bp = g_W23h + wz * 512 + lane;
#pragma unroll
            for (int ks = 0; ks < 8; ks++) {
                uint32_t a[4];
                a[0] = valid ? *(const uint32_t*)(Ab + ks * 32) : 0u;
                a[1] = 0u;                      // rows 8..15 padding
                a[2] = valid ? *(const uint32_t*)(Ab + ks * 32 + 16) : 0u;
                a[3] = 0u;
#pragma unroll
                for (int ntp = 0; ntp < 2; ntp++) {
                    uint4 bb = Bp[ntp * 256 + ks * 32];
                    mma_f16(zacc[2 * ntp + 0], a, bb.x, bb.y);
                    mma_f16(zacc[2 * ntp + 1], a, bb.z, bb.w);
                }
            }
            if (valid) {
#pragma unroll
                for (int nt = 0; nt < 4; nt++) {
                    int e = wz * 32 + nt * 8 + tg * 2;
                    float2 v = make_float2(0.1f * zacc[nt][0], 0.1f * zacc[nt][1]);
                    if (e < 128) *(float2*)(sZ2 + g * ND + e) = v;
                    else         *(float2*)(sZ3 + g * ND + (e - 128)) = v;
                }
            }
        }
    }
    // (no barrier: sZ consumed after the post-GEMM barrier)

    // ---- main GEMM: warp tile 64x64: fp16(u) @ fp16(W1+I)^T ----
    const int warpM = w >> 1, warpE = w & 1;

    float acc[4][8][4];
#pragma unroll
    for (int mt = 0; mt < 4; mt++)
#pragma unroll
        for (int nt = 0; nt < 8; nt++)
#pragma unroll
            for (int r = 0; r < 4; r++) acc[mt][nt][r] = 0.f;

    const char*  Abase = smem + SUH + (warpM * 64 + g) * ROWH + tg * 4;
    const uint4* Bbase = g_W1h + warpE * 1024 + lane;

#pragma unroll
    for (int ks = 0; ks < 8; ks++) {
        uint32_t a[4][4];
#pragma unroll
        for (int mt = 0; mt < 4; mt++) {
            const char* ar = Abase + mt * 16 * ROWH + ks * 32;
            a[mt][0] = *(const uint32_t*)(ar);
            a[mt][1] = *(const uint32_t*)(ar + 8 * ROWH);
            a[mt][2] = *(const uint32_t*)(ar + 16);
            a[mt][3] = *(const uint32_t*)(ar + 8 * ROWH + 16);
        }
#pragma unroll
        for (int ntp = 0; ntp < 4; ntp++) {
            uint4 bb = Bbase[ntp * 256 + ks * 32];
#pragma unroll
            for (int mt = 0; mt < 4; mt++) {
                mma_f16(acc[mt][2 * ntp + 0], a[mt], bb.x, bb.y);
                mma_f16(acc[mt][2 * ntp + 1], a[mt], bb.z, bb.w);
            }
        }
    }

    __syncthreads();   // sZ2/sZ3 visible

    // ---- epilogue: + b1 + mask*z3 + (c==mycol)*z2 (residual in GEMM) ----
    const int nA = warpM * 2, nB = nA + 1;
    const int colA = __ldg(coloring + nodeBase + nA);
    const int colB = __ldg(coloring + nodeBase + nB);

    float mk[4][2];
    bool  hit[4][2];
    int   lrow[4][2];
#pragma unroll
    for (int mt = 0; mt < 4; mt++)
#pragma unroll
        for (int half = 0; half < 2; half++) {
            int r = warpM * 64 + mt * 16 + half * 8 + g;
            int c = r & 31;
            lrow[mt][half] = r;
            mk[mt][half]  = __ldg(mask + rowBase + r);
            hit[mt][half] = (c == ((mt < 2) ? colA : colB));
        }

#pragma unroll
    for (int nt = 0; nt < 8; nt++) {
        const int e = warpE * 64 + nt * 8 + tg * 2;
        const float2 bv   = *(const float2*)(sB1 + e);
        const float2 z2A  = *(const float2*)(sZ2 + nA * ND + e);
        const float2 z3A  = *(const float2*)(sZ3 + nA * ND + e);
        const float2 z2B  = *(const float2*)(sZ2 + nB * ND + e);
        const float2 z3B  = *(const float2*)(sZ3 + nB * ND + e);
#pragma unroll
        for (int mt = 0; mt < 4; mt++) {
            const float2 z2v = (mt < 2) ? z2A : z2B;
            const float2 z3v = (mt < 2) ? z3A : z3B;
#pragma unroll
            for (int half = 0; half < 2; half++) {
                const int r = lrow[mt][half];
                float v0 = acc[mt][nt][half * 2 + 0] + bv.x + mk[mt][half] * z3v.x;
                float v1 = acc[mt][nt][half * 2 + 1] + bv.y + mk[mt][half] * z3v.y;
                if (hit[mt][half]) { v0 += z2v.x; v1 += z2v.y; }
                __stcs((float2*)(out + (long long)(rowBase + r) * ND + e),
                       make_float2(v0, v1));   // streaming store
            }
        }
    }
}

// ============================================================================
extern "C" void kernel_launch(void* const* d_in, const int* in_sizes, int n_in,
                              void* d_out, int out_size) {
    const float* u    = (const float*)d_in[0];
    const float* mask = (const float*)d_in[1];
    const float* norm = (const float*)d_in[2];
    const int*   col  = (const int*)d_in[3];
    const float* W1   = (const float*)d_in[4];
    const float* b1   = (const float*)d_in[5];
    const float* W2   = (const float*)d_in[6];
    const float* W3   = (const float*)d_in[7];
    float* out = (float*)d_out;

    static bool attr_set = false;
    if (!attr_set) {
        cudaFuncSetAttribute(fused_kernel,
                             cudaFuncAttributeMaxDynamicSharedMemorySize,
                             SMEM_BYTES);
        attr_set = true;
    }

    prep_kernel<<<24, 256>>>(W1, W2, W3);
    fused_kernel<<<NNODES / 4, 128, SMEM_BYTES>>>(u, mask, norm, col, b1, out);

    (void)in_sizes; (void)n_in; (void)out_size;
}

// round 15
// speedup vs baseline: 1.2151x; 1.0182x over previous
#include <cuda_runtime.h>
#include <cuda_fp16.h>
#include <cstdint>

#define NNODES 20000
#define NC 32
#define ND 128
#define ROWH 272        // fp16 smem row pitch in BYTES (136 halfs): conflict-free

// ---- smem byte offsets ----
#define SUH 0                    // fp16 u tile 128 x 272 = 34816
#define SMH 34816                // fp16 mean 4 x 272     = 1088
#define SZ2 35904                // fp32 z2 4 x 128 x 4   = 2048
#define SZ3 37952                // fp32 z3               = 2048
#define SB1 40000                // fp32 b1               = 512
#define SMEM_BYTES 40512         // x4 CTAs = 162048 <= 228KB/SM

// ---- device scratch: fragment-permuted fp16 weights (round-7 layout) ----
__device__ uint4 g_W1h[2048];    // 32 KB  (W1 + I folded)
__device__ uint4 g_W23h[4096];   // 64 KB  ([W2;W3])

__device__ __forceinline__ uint32_t pk(float a, float b) {
    __half2 h = __floats2half2_rn(a, b);
    return *(uint32_t*)&h;
}

// f32-accumulate variant (z-phase keeps full precision)
__device__ __forceinline__ void mma_f16(float* d, const uint32_t* a,
                                        uint32_t b0, uint32_t b1) {
    asm volatile(
        "mma.sync.aligned.m16n8k16.row.col.f32.f16.f16.f32 "
        "{%0,%1,%2,%3}, {%4,%5,%6,%7}, {%8,%9}, {%0,%1,%2,%3};\n"
        : "+f"(d[0]), "+f"(d[1]), "+f"(d[2]), "+f"(d[3])
        : "r"(a[0]), "r"(a[1]), "r"(a[2]), "r"(a[3]), "r"(b0), "r"(b1));
}

// f16-accumulate variant (main GEMM: halves acc regs, 2x HMMA rate)
__device__ __forceinline__ void mma_f16c(uint32_t* d, const uint32_t* a,
                                         uint32_t b0, uint32_t b1) {
    asm volatile(
        "mma.sync.aligned.m16n8k16.row.col.f16.f16.f16.f16 "
        "{%0,%1}, {%2,%3,%4,%5}, {%6,%7}, {%0,%1};\n"
        : "+r"(d[0]), "+r"(d[1])
        : "r"(a[0]), "r"(a[1]), "r"(a[2]), "r"(a[3]), "r"(b0), "r"(b1));
}

// ============================================================================
// prep: fragment-permuted fp16 weight images; W1 gets +I (residual folded)
// ============================================================================
__global__ void prep_kernel(const float* __restrict__ W1,
                            const float* __restrict__ W2,
                            const float* __restrict__ W3) {
    int t0 = blockIdx.x * blockDim.x + threadIdx.x;
    int stride = gridDim.x * blockDim.x;
    for (int i = t0; i < 2048; i += stride) {
        int lane = i & 31, ks = (i >> 5) & 7, ntp = (i >> 8) & 3, wE = i >> 10;
        int g = lane >> 2, tg = lane & 3;
        int e0 = wE * 64 + ntp * 16 + g, e1 = e0 + 8;
        int kb = ks * 16 + 2 * tg;
        uint4 v;
        v.x = pk(W1[e0 * ND + kb]     + (e0 == kb     ? 1.f : 0.f),
                 W1[e0 * ND + kb + 1] + (e0 == kb + 1 ? 1.f : 0.f));
        v.y = pk(W1[e0 * ND + kb + 8] + (e0 == kb + 8 ? 1.f : 0.f),
                 W1[e0 * ND + kb + 9] + (e0 == kb + 9 ? 1.f : 0.f));
        v.z = pk(W1[e1 * ND + kb]     + (e1 == kb     ? 1.f : 0.f),
                 W1[e1 * ND + kb + 1] + (e1 == kb + 1 ? 1.f : 0.f));
        v.w = pk(W1[e1 * ND + kb + 8] + (e1 == kb + 8 ? 1.f : 0.f),
                 W1[e1 * ND + kb + 9] + (e1 == kb + 9 ? 1.f : 0.f));
        g_W1h[i] = v;
    }
    for (int i = t0; i < 4096; i += stride) {
        int lane = i & 31, ks = (i >> 5) & 7, ntp = (i >> 8) & 1, w = i >> 9;
        int g = lane >> 2, tg = lane & 3;
        int e0 = w * 32 + ntp * 16 + g, e1 = e0 + 8;
        int kb = ks * 16 + 2 * tg;
        const float* r0 = (e0 < 128) ? (W2 + e0 * ND) : (W3 + (e0 - 128) * ND);
        const float* r1 = (e1 < 128) ? (W2 + e1 * ND) : (W3 + (e1 - 128) * ND);
        uint4 v;
        v.x = pk(r0[kb], r0[kb + 1]);
        v.y = pk(r0[kb + 8], r0[kb + 9]);
        v.z = pk(r1[kb], r1[kb + 1]);
        v.w = pk(r1[kb + 8], r1[kb + 9]);
        g_W23h[i] = v;
    }
}

// ============================================================================
// Fused kernel (round-11 structure): 4 nodes (128 rows)/CTA, 128 threads,
// 64x64 warp tiles, warp-per-node staging with fused mean.
// NEW: main GEMM accumulates in f16 (acc regs halved) -> 4 CTAs/SM.
// ============================================================================
__global__ void __launch_bounds__(128, 4)
fused_kernel(const float* __restrict__ u,
             const float* __restrict__ mask,
             const float* __restrict__ normalizer,
             const int* __restrict__ coloring,
             const float* __restrict__ b1,
             float* __restrict__ out) {
    extern __shared__ char smem[];
    float* sZ2 = (float*)(smem + SZ2);
    float* sZ3 = (float*)(smem + SZ3);
    float* sB1 = (float*)(smem + SB1);

    const int t = threadIdx.x;
    const int rowBase = blockIdx.x * 128;
    const int nodeBase = blockIdx.x * 4;

    const int w = t >> 5, lane = t & 31;
    const int g = lane >> 2, tg = lane & 3;

    // ---- stage u -> fp16 tile, warp = node, mean fused into the load ----
    {
        const float4* up = (const float4*)(u + (long long)(nodeBase + w) * (NC * ND)) + lane;
        char* rowp = smem + SUH + (w * 32) * ROWH + lane * 8;
        float4 s = make_float4(0.f, 0.f, 0.f, 0.f);
#pragma unroll
        for (int c = 0; c < NC; c++) {
            float4 v = up[c * 32];
            s.x += v.x; s.y += v.y; s.z += v.z; s.w += v.w;
            uint2 h;
            h.x = pk(v.x, v.y);
            h.y = pk(v.z, v.w);
            *(uint2*)(rowp + c * ROWH) = h;
        }
        const float inv = 1.f / normalizer[nodeBase + w];
        uint2 m;
        m.x = pk(s.x * inv, s.y * inv);
        m.y = pk(s.z * inv, s.w * inv);
        *(uint2*)(smem + SMH + w * ROWH + lane * 8) = m;
    }
    if (t < 32) *(float4*)(sB1 + t * 4) = ((const float4*)b1)[t];
    __syncthreads();

    // ---- z2/z3: mean(4x128, M-pad 16) @ [W2;W3]^T via fp16 mma (f32 acc) ----
    {
        const char* Ab = smem + SMH + g * ROWH + tg * 4;
        const bool valid = (g < 4);
#pragma unroll
        for (int rep = 0; rep < 2; rep++) {
            const int wz = w + rep * 4;        // e-slice 0..7
            float zacc[4][4];
#pragma unroll
            for (int n = 0; n < 4; n++)
#pragma unroll
                for (int r = 0; r < 4; r++) zacc[n][r] = 0.f;

            const uint4* Bp = g_W23h + wz * 512 + lane;
#pragma unroll
            for (int ks = 0; ks < 8; ks++) {
                uint32_t a[4];
                a[0] = valid ? *(const uint32_t*)(Ab + ks * 32) : 0u;
                a[1] = 0u;                      // rows 8..15 padding
                a[2] = valid ? *(const uint32_t*)(Ab + ks * 32 + 16) : 0u;
                a[3] = 0u;
#pragma unroll
                for (int ntp = 0; ntp < 2; ntp++) {
                    uint4 bb = Bp[ntp * 256 + ks * 32];
                    mma_f16(zacc[2 * ntp + 0], a, bb.x, bb.y);
                    mma_f16(zacc[2 * ntp + 1], a, bb.z, bb.w);
                }
            }
            if (valid) {
#pragma unroll
                for (int nt = 0; nt < 4; nt++) {
                    int e = wz * 32 + nt * 8 + tg * 2;
                    float2 v = make_float2(0.1f * zacc[nt][0], 0.1f * zacc[nt][1]);
                    if (e < 128) *(float2*)(sZ2 + g * ND + e) = v;
                    else         *(float2*)(sZ3 + g * ND + (e - 128)) = v;
                }
            }
        }
    }
    // (no barrier: sZ consumed after the post-GEMM barrier)

    // ---- main GEMM: warp tile 64x64: fp16(u) @ fp16(W1+I)^T, f16 acc ----
    const int warpM = w >> 1, warpE = w & 1;

    uint32_t acc[4][8][2];      // f16x2 pairs: [mt][nt][rowhalf]
#pragma unroll
    for (int mt = 0; mt < 4; mt++)
#pragma unroll
        for (int nt = 0; nt < 8; nt++) {
            acc[mt][nt][0] = 0u;
            acc[mt][nt][1] = 0u;
        }

    const char*  Abase = smem + SUH + (warpM * 64 + g) * ROWH + tg * 4;
    const uint4* Bbase = g_W1h + warpE * 1024 + lane;

#pragma unroll
    for (int ks = 0; ks < 8; ks++) {
        uint32_t a[4][4];
#pragma unroll
        for (int mt = 0; mt < 4; mt++) {
            const char* ar = Abase + mt * 16 * ROWH + ks * 32;
            a[mt][0] = *(const uint32_t*)(ar);
            a[mt][1] = *(const uint32_t*)(ar + 8 * ROWH);
            a[mt][2] = *(const uint32_t*)(ar + 16);
            a[mt][3] = *(const uint32_t*)(ar + 8 * ROWH + 16);
        }
#pragma unroll
        for (int ntp = 0; ntp < 4; ntp++) {
            uint4 bb = Bbase[ntp * 256 + ks * 32];
#pragma unroll
            for (int mt = 0; mt < 4; mt++) {
                mma_f16c(acc[mt][2 * ntp + 0], a[mt], bb.x, bb.y);
                mma_f16c(acc[mt][2 * ntp + 1], a[mt], bb.z, bb.w);
            }
        }
    }

    __syncthreads();   // sZ2/sZ3 visible

    // ---- epilogue: unpack f16 acc -> fp32; + b1 + mask*z3 + color-hit z2 ----
    const int nA = warpM * 2, nB = nA + 1;
    const int colA = __ldg(coloring + nodeBase + nA);
    const int colB = __ldg(coloring + nodeBase + nB);

    float mk[4][2];
    bool  hit[4][2];
    int   lrow[4][2];
#pragma unroll
    for (int mt = 0; mt < 4; mt++)
#pragma unroll
        for (int half = 0; half < 2; half++) {
            int r = warpM * 64 + mt * 16 + half * 8 + g;
            int c = r & 31;
            lrow[mt][half] = r;
            mk[mt][half]  = __ldg(mask + rowBase + r);
            hit[mt][half] = (c == ((mt < 2) ? colA : colB));
        }

#pragma unroll
    for (int nt = 0; nt < 8; nt++) {
        const int e = warpE * 64 + nt * 8 + tg * 2;
        const float2 bv   = *(const float2*)(sB1 + e);
        const float2 z2A  = *(const float2*)(sZ2 + nA * ND + e);
        const float2 z3A  = *(const float2*)(sZ3 + nA * ND + e);
        const float2 z2B  = *(const float2*)(sZ2 + nB * ND + e);
        const float2 z3B  = *(const float2*)(sZ3 + nB * ND + e);
#pragma unroll
        for (int mt = 0; mt < 4; mt++) {
            const float2 z2v = (mt < 2) ? z2A : z2B;
            const float2 z3v = (mt < 2) ? z3A : z3B;
#pragma unroll
            for (int half = 0; half < 2; half++) {
                const int r = lrow[mt][half];
                const float2 av = __half22float2(
                    *(const __half2*)&acc[mt][nt][half]);
                float v0 = av.x + bv.x + mk[mt][half] * z3v.x;
                float v1 = av.y + bv.y + mk[mt][half] * z3v.y;
                if (hit[mt][half]) { v0 += z2v.x; v1 += z2v.y; }
                *(float2*)(out + (long long)(rowBase + r) * ND + e) =
                    make_float2(v0, v1);
            }
        }
    }
}

// ============================================================================
extern "C" void kernel_launch(void* const* d_in, const int* in_sizes, int n_in,
                              void* d_out, int out_size) {
    const float* u    = (const float*)d_in[0];
    const float* mask = (const float*)d_in[1];
    const float* norm = (const float*)d_in[2];
    const int*   col  = (const int*)d_in[3];
    const float* W1   = (const float*)d_in[4];
    const float* b1   = (const float*)d_in[5];
    const float* W2   = (const float*)d_in[6];
    const float* W3   = (const float*)d_in[7];
    float* out = (float*)d_out;

    static bool attr_set = false;
    if (!attr_set) {
        cudaFuncSetAttribute(fused_kernel,
                             cudaFuncAttributeMaxDynamicSharedMemorySize,
                             SMEM_BYTES);
        attr_set = true;
    }

    prep_kernel<<<24, 256>>>(W1, W2, W3);
    fused_kernel<<<NNODES / 4, 128, SMEM_BYTES>>>(u, mask, norm, col, b1, out);

    (void)in_sizes; (void)n_in; (void)out_size;
}